// round 16
// baseline (speedup 1.0000x reference)
#include <cuda_runtime.h>

// LSTM T=512, B=4096, I=10, H=20.
// R16: WARP-AUTONOMOUS. No __syncthreads anywhere in the loop.
// Each warp owns 2 batch rows end-to-end. 96 padded gate-rows (4 gates x 24),
// 3 per lane (weights register-resident, ~96 regs). Gates exchanged through
// warp-private smem with __syncwarp only (2/step). Update spread 40 items
// over 32 lanes. Distance-2 x prefetch via warp-private smem (R12 pattern).
// fma.rn.f32x2; tanh.approx. 512 CTAs = one wave at (128,4) = 16 warps/SM.

#define T_STEPS 512
#define BATCH   4096
#define ISZ     10
#define HSZ     20
#define JPAD    24
#define ROWS_CTA 8
#define NTHREADS 128

// per-warp smem floats (warp stride 352 == 0 mod 32 -> bank math holds):
//   hb  at   0: [2 rows][H_ROW=20]            (40, single-buffered)
//   gb  at  64: rows at +0 / +G_ROW=116       (212; 116%32=20 -> rows disjoint)
//   xs  at 288: [2 bufs][2 rows][12]          (48)
#define W_STRIDE 352
#define H_ROW   20
#define G_OFF   64
#define G_ROW   116
#define X_OFF   288
#define XS_ROW  12
#define XS_BUF  24

typedef unsigned long long u64;

__device__ __forceinline__ u64 pack2(float x, float y) {
    u64 r; asm("mov.b64 %0, {%1,%2};" : "=l"(r) : "f"(x), "f"(y)); return r;
}
__device__ __forceinline__ void unpack2(u64 v, float& x, float& y) {
    asm("mov.b64 {%0,%1}, %2;" : "=f"(x), "=f"(y) : "l"(v));
}
__device__ __forceinline__ u64 ffma2(u64 a, u64 b, u64 c) {
    u64 r; asm("fma.rn.f32x2 %0, %1, %2, %3;" : "=l"(r) : "l"(a), "l"(b), "l"(c));
    return r;
}
__device__ __forceinline__ float tanh_fast(float x) {
    float y; asm("tanh.approx.f32 %0, %1;" : "=f"(y) : "f"(x)); return y;
}

__global__ void __launch_bounds__(NTHREADS, 4) lstm_r16_kernel(
    const float* __restrict__ x,      // [T, B, I]
    const float* __restrict__ h0,     // [B, H]
    const float* __restrict__ c0,     // [B, H]
    const float* __restrict__ Wih,    // [4H, I]
    const float* __restrict__ Whh,    // [4H, H]
    const float* __restrict__ bih,    // [4H]
    const float* __restrict__ bhh,    // [4H]
    float* __restrict__ out,
    long long out_size)
{
    const int lane = threadIdx.x & 31;
    const int w    = threadIdx.x >> 5;
    const int bA   = blockIdx.x * ROWS_CTA + 2 * w;   // this warp's rows
    const int bB   = bA + 1;

    __shared__ __align__(16) float sm[4 * W_STRIDE];
    float* const hb  = sm + w * W_STRIDE;             // [2][H_ROW]
    float* const gb  = sm + w * W_STRIDE + G_OFF;     // rows at +0 / +G_ROW
    float* const xsb = sm + w * W_STRIDE + X_OFF;     // [2][2][12]

    // ---- weights: lane owns padded gate-rows 3L..3L+2 (all in gate L>>3) ----
    const int gate = lane >> 3;
    const float s_ = (gate == 2) ? 1.0f : 0.5f;   // act = fma(tanh(s*z), s, 1-s)
    const float o_ = 1.0f - s_;
    u64 wxr[3][5], whr[3][10], bias2[3];
#pragma unroll
    for (int rr = 0; rr < 3; rr++) {
        const int jj  = 3 * lane + rr - gate * JPAD;
        const int row = gate * HSZ + jj;
        if (jj < HSZ) {
            const float* wr = Wih + row * ISZ;
#pragma unroll
            for (int k = 0; k < 5; k++)
                wxr[rr][k] = *reinterpret_cast<const u64*>(wr + 2 * k);
            const float* wr2 = Whh + row * HSZ;
#pragma unroll
            for (int k = 0; k < 10; k++)
                whr[rr][k] = *reinterpret_cast<const u64*>(wr2 + 2 * k);
            bias2[rr] = pack2(bih[row] + bhh[row], 0.0f);
        } else {
#pragma unroll
            for (int k = 0; k < 5; k++)  wxr[rr][k] = 0ull;
#pragma unroll
            for (int k = 0; k < 10; k++) whr[rr][k] = 0ull;
            bias2[rr] = 0ull;
        }
    }

    // ---- update items: 40 = 2 rows x 20 units over 32 lanes ----
    const int  i0row = (lane < HSZ) ? 0 : 1;
    const int  i0j   = (lane < HSZ) ? lane : lane - HSZ;
    const bool hasI1 = (lane < 8);
    const int  i1j   = lane + 12;                 // row 1 (B)
    const int  b0    = i0row ? bB : bA;

    float c0_ = c0[(size_t)b0 * HSZ + i0j], h0_ = 0.0f;
    hb[i0row * H_ROW + i0j] = h0[(size_t)b0 * HSZ + i0j];
    float c1_ = 0.0f, h1_ = 0.0f;
    if (hasI1) {
        c1_ = c0[(size_t)bB * HSZ + i1j];
        hb[H_ROW + i1j] = h0[(size_t)bB * HSZ + i1j];
    }

    // ---- x staging: 10 lanes, distance-2 pipeline ----
    const bool stager = (lane < 10);
    const int  srow   = lane / 5;
    const int  schk   = lane - srow * 5;
    const int  sgoff  = srow * ISZ + schk * 2;
    const int  sxoff  = srow * XS_ROW + schk * 2;
    const float* xwarp = x + (size_t)bA * ISZ;       // rows bA,bB contiguous
    const size_t x_step = (size_t)BATCH * ISZ;
    const float* const xclamp = xwarp + (size_t)(T_STEPS - 1) * x_step;

    u64 xp = 0ull;                                   // holds x(t+1)
    if (stager) {
        *reinterpret_cast<u64*>(xsb + sxoff) =
            __ldcg(reinterpret_cast<const u64*>(xwarp + sgoff));       // x(0)
        xp = __ldcg(reinterpret_cast<const u64*>(xwarp + x_step + sgoff)); // x(1)
    }
    __syncwarp();

    float* op0 = out + (size_t)b0 * HSZ + i0j;
    float* op1 = out + (size_t)bB * HSZ + i1j;
    const size_t o_step = (size_t)BATCH * HSZ;
    const float* xq = xwarp + 2 * x_step;            // -> x(t+2)

    // ================= one step body (XIN/XOUT immediates) =================
#define BODY(XIN, XOUT)                                                        \
    {                                                                          \
        const float* xquse = (xq <= xclamp) ? xq : xclamp;                     \
        u64 xnew = 0ull;                                                       \
        if (stager)                                                            \
            xnew = __ldcg(reinterpret_cast<const u64*>(xquse + sgoff));        \
        /* front-batch h loads (both rows) */                                  \
        ulonglong2 hva[5], hvb[5];                                             \
        _Pragma("unroll")                                                      \
        for (int k4 = 0; k4 < 5; k4++) {                                       \
            hva[k4] = *reinterpret_cast<const ulonglong2*>(hb + 4 * k4);       \
            hvb[k4] = *reinterpret_cast<const ulonglong2*>(hb + H_ROW + 4 * k4); \
        }                                                                      \
        /* ---- row A gates ---- */                                            \
        {                                                                      \
            const float* xr = xsb + (XIN);                                     \
            const ulonglong2 x01 = *reinterpret_cast<const ulonglong2*>(xr);   \
            const ulonglong2 x23 = *reinterpret_cast<const ulonglong2*>(xr + 4); \
            const u64        x4  = *reinterpret_cast<const u64*>(xr + 8);      \
            u64 a0 = bias2[0], a1 = bias2[1], a2 = bias2[2];                   \
            a0 = ffma2(wxr[0][0], x01.x, a0); a1 = ffma2(wxr[1][0], x01.x, a1); a2 = ffma2(wxr[2][0], x01.x, a2); \
            a0 = ffma2(wxr[0][1], x01.y, a0); a1 = ffma2(wxr[1][1], x01.y, a1); a2 = ffma2(wxr[2][1], x01.y, a2); \
            a0 = ffma2(wxr[0][2], x23.x, a0); a1 = ffma2(wxr[1][2], x23.x, a1); a2 = ffma2(wxr[2][2], x23.x, a2); \
            a0 = ffma2(wxr[0][3], x23.y, a0); a1 = ffma2(wxr[1][3], x23.y, a1); a2 = ffma2(wxr[2][3], x23.y, a2); \
            a0 = ffma2(wxr[0][4], x4,    a0); a1 = ffma2(wxr[1][4], x4,    a1); a2 = ffma2(wxr[2][4], x4,    a2); \
            _Pragma("unroll")                                                  \
            for (int k4 = 0; k4 < 5; k4++) {                                   \
                a0 = ffma2(whr[0][2 * k4],     hva[k4].x, a0);                 \
                a1 = ffma2(whr[1][2 * k4],     hva[k4].x, a1);                 \
                a2 = ffma2(whr[2][2 * k4],     hva[k4].x, a2);                 \
                a0 = ffma2(whr[0][2 * k4 + 1], hva[k4].y, a0);                 \
                a1 = ffma2(whr[1][2 * k4 + 1], hva[k4].y, a1);                 \
                a2 = ffma2(whr[2][2 * k4 + 1], hva[k4].y, a2);                 \
            }                                                                  \
            float lo, hi;                                                      \
            unpack2(a0, lo, hi); gb[3 * lane + 0] = fmaf(tanh_fast(s_ * (lo + hi)), s_, o_); \
            unpack2(a1, lo, hi); gb[3 * lane + 1] = fmaf(tanh_fast(s_ * (lo + hi)), s_, o_); \
            unpack2(a2, lo, hi); gb[3 * lane + 2] = fmaf(tanh_fast(s_ * (lo + hi)), s_, o_); \
        }                                                                      \
        /* ---- row B gates ---- */                                            \
        {                                                                      \
            const float* xr = xsb + (XIN) + XS_ROW;                            \
            const ulonglong2 x01 = *reinterpret_cast<const ulonglong2*>(xr);   \
            const ulonglong2 x23 = *reinterpret_cast<const ulonglong2*>(xr + 4); \
            const u64        x4  = *reinterpret_cast<const u64*>(xr + 8);      \
            u64 a0 = bias2[0], a1 = bias2[1], a2 = bias2[2];                   \
            a0 = ffma2(wxr[0][0], x01.x, a0); a1 = ffma2(wxr[1][0], x01.x, a1); a2 = ffma2(wxr[2][0], x01.x, a2); \
            a0 = ffma2(wxr[0][1], x01.y, a0); a1 = ffma2(wxr[1][1], x01.y, a1); a2 = ffma2(wxr[2][1], x01.y, a2); \
            a0 = ffma2(wxr[0][2], x23.x, a0); a1 = ffma2(wxr[1][2], x23.x, a1); a2 = ffma2(wxr[2][2], x23.x, a2); \
            a0 = ffma2(wxr[0][3], x23.y, a0); a1 = ffma2(wxr[1][3], x23.y, a1); a2 = ffma2(wxr[2][3], x23.y, a2); \
            a0 = ffma2(wxr[0][4], x4,    a0); a1 = ffma2(wxr[1][4], x4,    a1); a2 = ffma2(wxr[2][4], x4,    a2); \
            _Pragma("unroll")                                                  \
            for (int k4 = 0; k4 < 5; k4++) {                                   \
                a0 = ffma2(whr[0][2 * k4],     hvb[k4].x, a0);                 \
                a1 = ffma2(whr[1][2 * k4],     hvb[k4].x, a1);                 \
                a2 = ffma2(whr[2][2 * k4],     hvb[k4].x, a2);                 \
                a0 = ffma2(whr[0][2 * k4 + 1], hvb[k4].y, a0);                 \
                a1 = ffma2(whr[1][2 * k4 + 1], hvb[k4].y, a1);                 \
                a2 = ffma2(whr[2][2 * k4 + 1], hvb[k4].y, a2);                 \
            }                                                                  \
            float lo, hi;                                                      \
            unpack2(a0, lo, hi); gb[G_ROW + 3 * lane + 0] = fmaf(tanh_fast(s_ * (lo + hi)), s_, o_); \
            unpack2(a1, lo, hi); gb[G_ROW + 3 * lane + 1] = fmaf(tanh_fast(s_ * (lo + hi)), s_, o_); \
            unpack2(a2, lo, hi); gb[G_ROW + 3 * lane + 2] = fmaf(tanh_fast(s_ * (lo + hi)), s_, o_); \
        }                                                                      \
        /* stage x(t+1) into the other buffer */                               \
        if (stager)                                                            \
            *reinterpret_cast<u64*>(xsb + (XOUT) + sxoff) = xp;                \
        xp = xnew;                                                             \
        __syncwarp();   /* gates + x(t+1) visible; h/x reads done */           \
        /* ---- update: item0 (all lanes) + item1 (lanes 0-7) ---- */          \
        {                                                                      \
            const float* gp = gb + i0row * G_ROW + i0j;                        \
            const float gi = gp[0];                                            \
            const float gf = gp[JPAD];                                         \
            const float gg = gp[2 * JPAD];                                     \
            const float go = gp[3 * JPAD];                                     \
            c0_ = fmaf(gf, c0_, gi * gg);                                      \
            h0_ = go * tanh_fast(c0_);                                         \
            hb[i0row * H_ROW + i0j] = h0_;                                     \
            __stcs(op0, h0_);                                                  \
            if (hasI1) {                                                       \
                const float* g1 = gb + G_ROW + i1j;                            \
                const float gi1 = g1[0];                                       \
                const float gf1 = g1[JPAD];                                    \
                const float gg1 = g1[2 * JPAD];                                \
                const float go1 = g1[3 * JPAD];                                \
                c1_ = fmaf(gf1, c1_, gi1 * gg1);                               \
                h1_ = go1 * tanh_fast(c1_);                                    \
                hb[H_ROW + i1j] = h1_;                                         \
                __stcs(op1, h1_);                                              \
            }                                                                  \
        }                                                                      \
        __syncwarp();   /* h(t+1) visible */                                   \
        op0 += o_step; op1 += o_step;                                          \
        xq += x_step;                                                          \
    }
    // ========================================================================

    for (int it = 0; it < T_STEPS / 2; ++it) {
        BODY(0, XS_BUF);     // even t: x from buf0, stage x(t+1) -> buf1
        BODY(XS_BUF, 0);     // odd  t: x from buf1, stage x(t+1) -> buf0
    }
#undef BODY

    // ---- final h, c appended after outputs ----
    const long long base = (long long)T_STEPS * BATCH * HSZ;
    if (out_size >= base + 2LL * BATCH * HSZ) {
        out[base + (size_t)b0 * HSZ + i0j] = h0_;
        out[base + (size_t)BATCH * HSZ + (size_t)b0 * HSZ + i0j] = c0_;
        if (hasI1) {
            out[base + (size_t)bB * HSZ + i1j] = h1_;
            out[base + (size_t)BATCH * HSZ + (size_t)bB * HSZ + i1j] = c1_;
        }
    }
}

extern "C" void kernel_launch(void* const* d_in, const int* in_sizes, int n_in,
                              void* d_out, int out_size) {
    const float* x   = (const float*)d_in[0];
    const float* h0  = (const float*)d_in[1];
    const float* c0  = (const float*)d_in[2];
    const float* Wih = (const float*)d_in[3];
    const float* Whh = (const float*)d_in[4];
    const float* bih = (const float*)d_in[5];
    const float* bhh = (const float*)d_in[6];
    float* out = (float*)d_out;

    dim3 grid(BATCH / ROWS_CTA);   // 512 CTAs -> one resident wave at 4 CTA/SM
    dim3 block(NTHREADS);          // 128 threads, 4 autonomous warps
    lstm_r16_kernel<<<grid, block>>>(x, h0, c0, Wih, Whh, bih, bhh,
                                     out, (long long)out_size);
}

// round 17
// speedup vs baseline: 1.3085x; 1.3085x over previous
#include <cuda_runtime.h>

// LSTM T=512, B=4096, I=10, H=20.
// R17: warp-autonomous (NO __syncthreads in loop), register-dieted R16.
// Warp owns 2 batch rows. 96 padded gate-rows (4 gates x 24), 3/lane, shared
// across both rows (weights 45 u64 + acc 6 u64). Single-buffered h and x
// (reads pre-sync1, writes between sync1/sync2). Bias in CTA smem table.
// Distance-2 x prefetch, guard t<510. fma.rn.f32x2; tanh.approx.
// 512 CTAs x 128 thr at (128,4) -> 16 warps/SM, one wave.

#define T_STEPS 512
#define BATCH   4096
#define ISZ     10
#define HSZ     20
#define JPAD    24
#define ROWS_CTA 8
#define NTHREADS 128

// per-warp smem floats (stride 288 == 0 mod 32):
//   gb rowA at +0, rowB at +GB_B=116 (116%32=20 -> all update LDS and hb STS
//   provably bank-disjoint per gate group), hb [2][20] at +216, xs [2][12] at +256
#define GB_B    116
#define HB_OFF  216
#define XS_OFF  256
#define W_STRIDE 288

typedef unsigned long long u64;

__device__ __forceinline__ u64 pack2(float x, float y) {
    u64 r; asm("mov.b64 %0, {%1,%2};" : "=l"(r) : "f"(x), "f"(y)); return r;
}
__device__ __forceinline__ void unpack2(u64 v, float& x, float& y) {
    asm("mov.b64 {%0,%1}, %2;" : "=f"(x), "=f"(y) : "l"(v));
}
__device__ __forceinline__ u64 ffma2(u64 a, u64 b, u64 c) {
    u64 r; asm("fma.rn.f32x2 %0, %1, %2, %3;" : "=l"(r) : "l"(a), "l"(b), "l"(c));
    return r;
}
__device__ __forceinline__ float tanh_fast(float x) {
    float y; asm("tanh.approx.f32 %0, %1;" : "=f"(y) : "f"(x)); return y;
}

__global__ void __launch_bounds__(NTHREADS, 4) lstm_r17_kernel(
    const float* __restrict__ x,      // [T, B, I]
    const float* __restrict__ h0,     // [B, H]
    const float* __restrict__ c0,     // [B, H]
    const float* __restrict__ Wih,    // [4H, I]
    const float* __restrict__ Whh,    // [4H, H]
    const float* __restrict__ bih,    // [4H]
    const float* __restrict__ bhh,    // [4H]
    float* __restrict__ out,
    long long out_size)
{
    const int lane = threadIdx.x & 31;
    const int w    = threadIdx.x >> 5;
    const int bA   = blockIdx.x * ROWS_CTA + 2 * w;
    const int bB   = bA + 1;

    __shared__ __align__(16) float sm[4 * W_STRIDE + 96];
    float* const gb   = sm + w * W_STRIDE;        // gates rowA +0, rowB +GB_B
    float* const hb   = gb + HB_OFF;              // h rowA +0, rowB +20
    float* const xs   = gb + XS_OFF;              // x rowA +0, rowB +12
    float* const bias_s = sm + 4 * W_STRIDE;      // CTA-shared bias table [96]

    // one-time bias table (padded rows -> 0)
    if (threadIdx.x < 96) {
        const int g  = threadIdx.x / JPAD;
        const int jj = threadIdx.x - g * JPAD;
        bias_s[threadIdx.x] =
            (jj < HSZ) ? bih[g * HSZ + jj] + bhh[g * HSZ + jj] : 0.0f;
    }

    // ---- weights: lane owns padded gate-rows 3L..3L+2 (single gate L>>3) ----
    const int gate = lane >> 3;
    const float s_ = (gate == 2) ? 1.0f : 0.5f;   // act = fma(tanh(s*z), s, 1-s)
    const float o_ = 1.0f - s_;
    u64 wxr[3][5], whr[3][10];
#pragma unroll
    for (int rr = 0; rr < 3; rr++) {
        const int jj  = 3 * lane + rr - gate * JPAD;
        const int row = gate * HSZ + jj;
        if (jj < HSZ) {
            const float* wr = Wih + row * ISZ;
#pragma unroll
            for (int k = 0; k < 5; k++)
                wxr[rr][k] = *reinterpret_cast<const u64*>(wr + 2 * k);
            const float* wr2 = Whh + row * HSZ;
#pragma unroll
            for (int k = 0; k < 10; k++)
                whr[rr][k] = *reinterpret_cast<const u64*>(wr2 + 2 * k);
        } else {
#pragma unroll
            for (int k = 0; k < 5; k++)  wxr[rr][k] = 0ull;
#pragma unroll
            for (int k = 0; k < 10; k++) whr[rr][k] = 0ull;
        }
    }

    // ---- update items: 40 = 2 rows x 20 units over 32 lanes ----
    const int  i0row = (lane < HSZ) ? 0 : 1;
    const int  i0j   = (lane < HSZ) ? lane : lane - HSZ;
    const bool hasI1 = (lane < 8);
    const int  i1j   = lane + 12;                 // always row B
    const int  b0    = i0row ? bB : bA;

    float c0_ = c0[(size_t)b0 * HSZ + i0j], h0_ = 0.0f;
    hb[i0row * HSZ + i0j] = h0[(size_t)b0 * HSZ + i0j];
    float c1_ = 0.0f, h1_ = 0.0f;
    if (hasI1) {
        c1_ = c0[(size_t)bB * HSZ + i1j];
        hb[HSZ + i1j] = h0[(size_t)bB * HSZ + i1j];
    }

    // ---- x staging: 10 lanes (5 per row), distance-2 pipeline ----
    const bool stager = (lane < 10);
    const int  srow   = lane / 5;
    const int  schk   = lane - srow * 5;
    const int  sgoff  = srow * ISZ + schk * 2;    // gmem float offset
    const int  sxoff  = srow * 12 + schk * 2;     // smem float offset
    const float* xwarp = x + (size_t)bA * ISZ;    // rows bA,bB contiguous (80B)
    const size_t x_step = (size_t)BATCH * ISZ;

    u64 xp = 0ull;                                // holds x(t+1)
    if (stager) {
        *reinterpret_cast<u64*>(xs + sxoff) =
            __ldcg(reinterpret_cast<const u64*>(xwarp + sgoff));           // x(0)
        xp = __ldcg(reinterpret_cast<const u64*>(xwarp + x_step + sgoff)); // x(1)
    }
    __syncthreads();   // one-time: bias table + per-warp init (outside loop)

    float* op0 = out + (size_t)b0 * HSZ + i0j;    // op1 == op0 + 32 (uniform)
    const size_t o_step = (size_t)BATCH * HSZ;
    const float* xq = xwarp + 2 * x_step;         // -> x(t+2)

    for (int t = 0; t < T_STEPS; ++t) {
        // prefetch x(t+2); last two steps skip (would be out of range)
        u64 xnew = 0ull;
        if (stager && t < T_STEPS - 2)
            xnew = __ldcg(reinterpret_cast<const u64*>(xq + sgoff));

        // accumulators seeded from smem bias table
        u64 aA0 = pack2(bias_s[3 * lane],     0.0f);
        u64 aA1 = pack2(bias_s[3 * lane + 1], 0.0f);
        u64 aA2 = pack2(bias_s[3 * lane + 2], 0.0f);
        u64 aB0 = aA0, aB1 = aA1, aB2 = aA2;

        // ---- x projection, row A then row B (broadcast LDS) ----
        {
            const ulonglong2 x01 = *reinterpret_cast<const ulonglong2*>(xs);
            const ulonglong2 x23 = *reinterpret_cast<const ulonglong2*>(xs + 4);
            const u64        x4  = *reinterpret_cast<const u64*>(xs + 8);
            aA0 = ffma2(wxr[0][0], x01.x, aA0); aA1 = ffma2(wxr[1][0], x01.x, aA1); aA2 = ffma2(wxr[2][0], x01.x, aA2);
            aA0 = ffma2(wxr[0][1], x01.y, aA0); aA1 = ffma2(wxr[1][1], x01.y, aA1); aA2 = ffma2(wxr[2][1], x01.y, aA2);
            aA0 = ffma2(wxr[0][2], x23.x, aA0); aA1 = ffma2(wxr[1][2], x23.x, aA1); aA2 = ffma2(wxr[2][2], x23.x, aA2);
            aA0 = ffma2(wxr[0][3], x23.y, aA0); aA1 = ffma2(wxr[1][3], x23.y, aA1); aA2 = ffma2(wxr[2][3], x23.y, aA2);
            aA0 = ffma2(wxr[0][4], x4,    aA0); aA1 = ffma2(wxr[1][4], x4,    aA1); aA2 = ffma2(wxr[2][4], x4,    aA2);
        }
        {
            const ulonglong2 x01 = *reinterpret_cast<const ulonglong2*>(xs + 12);
            const ulonglong2 x23 = *reinterpret_cast<const ulonglong2*>(xs + 16);
            const u64        x4  = *reinterpret_cast<const u64*>(xs + 20);
            aB0 = ffma2(wxr[0][0], x01.x, aB0); aB1 = ffma2(wxr[1][0], x01.x, aB1); aB2 = ffma2(wxr[2][0], x01.x, aB2);
            aB0 = ffma2(wxr[0][1], x01.y, aB0); aB1 = ffma2(wxr[1][1], x01.y, aB1); aB2 = ffma2(wxr[2][1], x01.y, aB2);
            aB0 = ffma2(wxr[0][2], x23.x, aB0); aB1 = ffma2(wxr[1][2], x23.x, aB1); aB2 = ffma2(wxr[2][2], x23.x, aB2);
            aB0 = ffma2(wxr[0][3], x23.y, aB0); aB1 = ffma2(wxr[1][3], x23.y, aB1); aB2 = ffma2(wxr[2][3], x23.y, aB2);
            aB0 = ffma2(wxr[0][4], x4,    aB0); aB1 = ffma2(wxr[1][4], x4,    aB1); aB2 = ffma2(wxr[2][4], x4,    aB2);
        }

        // ---- h projection, inline loads (no carried arrays) ----
#pragma unroll
        for (int k4 = 0; k4 < 5; k4++) {
            const ulonglong2 va = *reinterpret_cast<const ulonglong2*>(hb + 4 * k4);
            const ulonglong2 vb = *reinterpret_cast<const ulonglong2*>(hb + HSZ + 4 * k4);
            aA0 = ffma2(whr[0][2 * k4],     va.x, aA0);
            aA1 = ffma2(whr[1][2 * k4],     va.x, aA1);
            aA2 = ffma2(whr[2][2 * k4],     va.x, aA2);
            aA0 = ffma2(whr[0][2 * k4 + 1], va.y, aA0);
            aA1 = ffma2(whr[1][2 * k4 + 1], va.y, aA1);
            aA2 = ffma2(whr[2][2 * k4 + 1], va.y, aA2);
            aB0 = ffma2(whr[0][2 * k4],     vb.x, aB0);
            aB1 = ffma2(whr[1][2 * k4],     vb.x, aB1);
            aB2 = ffma2(whr[2][2 * k4],     vb.x, aB2);
            aB0 = ffma2(whr[0][2 * k4 + 1], vb.y, aB0);
            aB1 = ffma2(whr[1][2 * k4 + 1], vb.y, aB1);
            aB2 = ffma2(whr[2][2 * k4 + 1], vb.y, aB2);
        }

        // ---- activations + gate stores (stride-3, conflict-free) ----
        float lo, hi;
        unpack2(aA0, lo, hi); gb[3 * lane + 0] = fmaf(tanh_fast(s_ * (lo + hi)), s_, o_);
        unpack2(aA1, lo, hi); gb[3 * lane + 1] = fmaf(tanh_fast(s_ * (lo + hi)), s_, o_);
        unpack2(aA2, lo, hi); gb[3 * lane + 2] = fmaf(tanh_fast(s_ * (lo + hi)), s_, o_);
        unpack2(aB0, lo, hi); gb[GB_B + 3 * lane + 0] = fmaf(tanh_fast(s_ * (lo + hi)), s_, o_);
        unpack2(aB1, lo, hi); gb[GB_B + 3 * lane + 1] = fmaf(tanh_fast(s_ * (lo + hi)), s_, o_);
        unpack2(aB2, lo, hi); gb[GB_B + 3 * lane + 2] = fmaf(tanh_fast(s_ * (lo + hi)), s_, o_);

        __syncwarp();   // gates visible; all h/x reads of this step done

        // ---- update (item0: all lanes; item1: lanes 0-7) + x restage ----
        {
            const float* gp = gb + i0row * GB_B + i0j;
            const float gi = gp[0];
            const float gf = gp[JPAD];
            const float gg = gp[2 * JPAD];
            const float go = gp[3 * JPAD];
            c0_ = fmaf(gf, c0_, gi * gg);
            h0_ = go * tanh_fast(c0_);
            hb[i0row * HSZ + i0j] = h0_;
            __stcs(op0, h0_);
            if (hasI1) {
                const float* g1 = gb + GB_B + i1j;
                const float gi1 = g1[0];
                const float gf1 = g1[JPAD];
                const float gg1 = g1[2 * JPAD];
                const float go1 = g1[3 * JPAD];
                c1_ = fmaf(gf1, c1_, gi1 * gg1);
                h1_ = go1 * tanh_fast(c1_);
                hb[HSZ + i1j] = h1_;
                __stcs(op0 + 32, h1_);
            }
        }
        if (stager) {
            *reinterpret_cast<u64*>(xs + sxoff) = xp;   // x(t+1) into place
            xp = xnew;
        }

        __syncwarp();   // h(t+1), x(t+1) visible

        op0 += o_step;
        xq  += x_step;
    }

    // ---- final h, c appended after outputs ----
    const long long base = (long long)T_STEPS * BATCH * HSZ;
    if (out_size >= base + 2LL * BATCH * HSZ) {
        out[base + (size_t)b0 * HSZ + i0j] = h0_;
        out[base + (size_t)BATCH * HSZ + (size_t)b0 * HSZ + i0j] = c0_;
        if (hasI1) {
            out[base + (size_t)bB * HSZ + i1j] = h1_;
            out[base + (size_t)BATCH * HSZ + (size_t)bB * HSZ + i1j] = c1_;
        }
    }
}

extern "C" void kernel_launch(void* const* d_in, const int* in_sizes, int n_in,
                              void* d_out, int out_size) {
    const float* x   = (const float*)d_in[0];
    const float* h0  = (const float*)d_in[1];
    const float* c0  = (const float*)d_in[2];
    const float* Wih = (const float*)d_in[3];
    const float* Whh = (const float*)d_in[4];
    const float* bih = (const float*)d_in[5];
    const float* bhh = (const float*)d_in[6];
    float* out = (float*)d_out;

    dim3 grid(BATCH / ROWS_CTA);   // 512 CTAs -> one wave at 4 CTA/SM
    dim3 block(NTHREADS);          // 128 threads, 4 autonomous warps
    lstm_r17_kernel<<<grid, block>>>(x, h0, c0, Wih, Whh, bih, bhh,
                                     out, (long long)out_size);
}